// round 1
// baseline (speedup 1.0000x reference)
#include <cuda_runtime.h>
#include <math.h>

#define D 16
#define K 32
#define COEF_PER_K 153          // 16 rows of (neg_a_i + (i+1) M entries) = 152, + c_k
#define PPT 4                   // points per thread
#define TPB 256                 // threads per block (main kernel)
#define TILE (TPB * PPT)        // points per block-tile
#define LOG_2PI 1.8378770664093453f

__device__ float g_coef[K * COEF_PER_K];
__device__ float g_partial[8192];

// ---------------------------------------------------------------------------
// Setup: one block per component k.
//   cov = A A^T ; chol(cov) = L ; M = L^{-1} ; a = M mu ;
//   c_k = -sum(log L_ii) - 0.5*D*log(2pi) + lw_k^2
// Packed layout per k: for i in 0..15: [-a_i, M[i][0..i]], then c_k.
// ---------------------------------------------------------------------------
__global__ void mog_setup(const float* __restrict__ means,
                          const float* __restrict__ cov_parts,
                          const float* __restrict__ logw)
{
    const int k = blockIdx.x;
    const int t = threadIdx.x;

    __shared__ float A[D][D];
    __shared__ float C[D][D + 1];
    __shared__ float Mi[D][D + 1];

    // load A (256 floats with 256 threads)
    if (t < D * D) A[t / D][t % D] = cov_parts[k * D * D + t];
    __syncthreads();

    // cov = A A^T (one entry per thread)
    if (t < D * D) {
        int i = t / D, l = t % D;
        float s = 0.f;
        #pragma unroll
        for (int j = 0; j < D; j++) s += A[i][j] * A[l][j];
        C[i][l] = s;
    }
    __syncthreads();

    // in-place lower Cholesky
    for (int j = 0; j < D; j++) {
        if (t == 0) C[j][j] = sqrtf(C[j][j]);
        __syncthreads();
        if (t > j && t < D) C[t][j] = C[t][j] / C[j][j];
        __syncthreads();
        if (t > j && t < D) {
            for (int l = j + 1; l <= t; l++) C[t][l] -= C[t][j] * C[l][j];
        }
        __syncthreads();
    }

    // M = L^{-1}: thread c computes column c (forward substitution)
    if (t < D) {
        int c = t;
        for (int i = 0; i < c; i++) Mi[i][c] = 0.f;
        Mi[c][c] = 1.f / C[c][c];
        for (int i = c + 1; i < D; i++) {
            float s = 0.f;
            for (int j = c; j < i; j++) s += C[i][j] * Mi[j][c];
            Mi[i][c] = -s / C[i][i];
        }
    }
    __syncthreads();

    // pack coefficients (thread 0, tiny)
    if (t == 0) {
        float logdet = 0.f;
        for (int j = 0; j < D; j++) logdet += logf(C[j][j]);
        float lw = logw[k];
        float ck = -logdet - 0.5f * (float)D * LOG_2PI + lw * lw;

        int pos = k * COEF_PER_K;
        for (int i = 0; i < D; i++) {
            float ai = 0.f;
            for (int j = 0; j <= i; j++) ai += Mi[i][j] * means[k * D + j];
            g_coef[pos++] = -ai;
            for (int j = 0; j <= i; j++) g_coef[pos++] = Mi[i][j];
        }
        g_coef[pos] = ck;   // pos == k*153 + 152
    }
}

// ---------------------------------------------------------------------------
// Main: per point, quad_k = || M_k x - a_k ||^2, S = sum_k exp(-0.5 quad + c_k),
// acc += log(S). Each thread carries PPT=4 points in registers; coefficients
// come from shared memory with full-warp broadcast reads.
// ---------------------------------------------------------------------------
__global__ void __launch_bounds__(TPB)
mog_main(const float* __restrict__ data, int N, int nTiles)
{
    __shared__ float sc[K * COEF_PER_K];
    __shared__ float red[TPB];

    for (int i = threadIdx.x; i < K * COEF_PER_K; i += TPB) sc[i] = g_coef[i];
    __syncthreads();

    float acc = 0.f;

    for (int tile = blockIdx.x; tile < nTiles; tile += gridDim.x) {
        const int base = tile * TILE + threadIdx.x;

        float x[PPT][D];
        bool  valid[PPT];
        #pragma unroll
        for (int p = 0; p < PPT; p++) {
            int idx = base + p * TPB;
            valid[p] = (idx < N);
            int pt = valid[p] ? idx : (N - 1);      // clamp: no OOB loads
            const float4* src = (const float4*)(data + (size_t)pt * D);
            #pragma unroll
            for (int v = 0; v < 4; v++) {
                float4 f = src[v];
                x[p][v * 4 + 0] = f.x;
                x[p][v * 4 + 1] = f.y;
                x[p][v * 4 + 2] = f.z;
                x[p][v * 4 + 3] = f.w;
            }
        }

        float S[PPT];
        #pragma unroll
        for (int p = 0; p < PPT; p++) S[p] = 0.f;

        for (int k = 0; k < K; k++) {
            const float* w = sc + k * COEF_PER_K;
            float q[PPT];
            #pragma unroll
            for (int p = 0; p < PPT; p++) q[p] = 0.f;

            int off = 0;
            #pragma unroll
            for (int i = 0; i < D; i++) {
                float na = w[off++];                // -a_i
                float z[PPT];
                #pragma unroll
                for (int p = 0; p < PPT; p++) z[p] = na;
                #pragma unroll
                for (int j = 0; j <= i; j++) {
                    float m = w[off++];
                    #pragma unroll
                    for (int p = 0; p < PPT; p++) z[p] = fmaf(m, x[p][j], z[p]);
                }
                #pragma unroll
                for (int p = 0; p < PPT; p++) q[p] = fmaf(z[p], z[p], q[p]);
            }
            float ck = w[COEF_PER_K - 1];
            #pragma unroll
            for (int p = 0; p < PPT; p++) {
                S[p] += __expf(fmaf(q[p], -0.5f, ck));
            }
        }

        #pragma unroll
        for (int p = 0; p < PPT; p++) {
            if (valid[p]) acc += __logf(S[p]);
        }
    }

    // block tree reduction
    red[threadIdx.x] = acc;
    __syncthreads();
    for (int s = TPB / 2; s > 0; s >>= 1) {
        if (threadIdx.x < s) red[threadIdx.x] += red[threadIdx.x + s];
        __syncthreads();
    }
    if (threadIdx.x == 0) g_partial[blockIdx.x] = red[0];
}

// ---------------------------------------------------------------------------
// Final: deterministic double-precision reduction of block partials -> mean.
// ---------------------------------------------------------------------------
__global__ void mog_final(float* __restrict__ out, int N, int nBlocks)
{
    __shared__ double red[256];
    double s = 0.0;
    for (int i = threadIdx.x; i < nBlocks; i += 256) s += (double)g_partial[i];
    red[threadIdx.x] = s;
    __syncthreads();
    for (int st = 128; st > 0; st >>= 1) {
        if (threadIdx.x < st) red[threadIdx.x] += red[threadIdx.x + st];
        __syncthreads();
    }
    if (threadIdx.x == 0) out[0] = (float)(red[0] / (double)N);
}

// ---------------------------------------------------------------------------
extern "C" void kernel_launch(void* const* d_in, const int* in_sizes, int n_in,
                              void* d_out, int out_size)
{
    const float* data      = (const float*)d_in[0];
    const float* means     = (const float*)d_in[1];
    const float* cov_parts = (const float*)d_in[2];
    const float* logw      = (const float*)d_in[3];
    float* out = (float*)d_out;

    const int N = in_sizes[0] / D;

    mog_setup<<<K, 256>>>(means, cov_parts, logw);

    int nTiles = (N + TILE - 1) / TILE;
    int blocks = nTiles < 1776 ? nTiles : 1776;
    mog_main<<<blocks, TPB>>>(data, N, nTiles);

    mog_final<<<1, 256>>>(out, N, blocks);
}